// round 2
// baseline (speedup 1.0000x reference)
#include <cuda_runtime.h>
#include <math.h>

#define DM 768
#define DFF 3072
#define NH 12
#define DK 64
#define BATCH 2
#define SEQ 2048
#define MROWS (BATCH*SEQ)            // 4096
#define BHN (BATCH*NH)               // 24
#define OUT_ELEMS (MROWS*DM)         // 3145728
#define ATT_ELEMS ((size_t)BHN*SEQ*SEQ) // 100663296

// ---- scratch (allocation-free: __device__ globals) ----
__device__ float g_Q[MROWS*DM];
__device__ float g_K[MROWS*DM];
__device__ float g_V[MROWS*DM];
__device__ float g_P[BHN*(size_t)SEQ*SEQ];   // used only if attn not in d_out
__device__ float g_ctx[MROWS*DM];
__device__ float g_t0[MROWS*DM];
__device__ float g_ao[MROWS*DM];
__device__ float g_h[MROWS*DFF];
__device__ float g_f[MROWS*DM];

// ============================================================
// Generic 128x128x8 SGEMM: C = A[M,K] @ B[K,N] + bias (+resid) (+relu)
// M,N multiples of 128; K multiple of 8.
// ============================================================
template<bool RELU>
__global__ __launch_bounds__(256) void sgemm128(
    const float* __restrict__ A, const float* __restrict__ Bm,
    const float* __restrict__ bias, const float* __restrict__ resid,
    float* __restrict__ C, int M, int N, int K)
{
    __shared__ float As[8][128];
    __shared__ float Bs[8][128];
    int tid = threadIdx.x;
    int bm = blockIdx.y * 128;
    int bn = blockIdx.x * 128;
    int tx = tid & 15, ty = tid >> 4;
    int mo = ty * 8, no = tx * 8;

    float acc[8][8];
#pragma unroll
    for (int i = 0; i < 8; i++)
#pragma unroll
        for (int j = 0; j < 8; j++) acc[i][j] = 0.f;

    int arow = tid >> 1, akc = (tid & 1) * 4;       // A tile: 128 rows x 8 k
    int brow = tid >> 5, bcol = (tid & 31) * 4;     // B tile: 8 k x 128 cols
    const float* Aptr = A + (size_t)(bm + arow) * K + akc;
    const float* Bptr = Bm + (size_t)brow * N + bn + bcol;

    for (int k0 = 0; k0 < K; k0 += 8) {
        float4 av = *(const float4*)Aptr; Aptr += 8;
        float4 bv = *(const float4*)Bptr; Bptr += (size_t)8 * N;
        __syncthreads();
        As[akc + 0][arow] = av.x;
        As[akc + 1][arow] = av.y;
        As[akc + 2][arow] = av.z;
        As[akc + 3][arow] = av.w;
        *(float4*)&Bs[brow][bcol] = bv;
        __syncthreads();
#pragma unroll
        for (int kk = 0; kk < 8; kk++) {
            float a[8], bb[8];
            *(float4*)&a[0]  = *(const float4*)&As[kk][mo];
            *(float4*)&a[4]  = *(const float4*)&As[kk][mo + 4];
            *(float4*)&bb[0] = *(const float4*)&Bs[kk][no];
            *(float4*)&bb[4] = *(const float4*)&Bs[kk][no + 4];
#pragma unroll
            for (int i = 0; i < 8; i++)
#pragma unroll
                for (int j = 0; j < 8; j++)
                    acc[i][j] += a[i] * bb[j];
        }
    }

#pragma unroll
    for (int i = 0; i < 8; i++) {
        int gm = bm + mo + i;
#pragma unroll
        for (int j = 0; j < 8; j++) {
            int gn = bn + no + j;
            float v = acc[i][j] + bias[gn];
            size_t idx = (size_t)gm * N + gn;
            if (resid) v += resid[idx];
            if (RELU) v = fmaxf(v, 0.f);
            C[idx] = v;
        }
    }
}

// ============================================================
// Scores: P[bh,q,k] = (Q_bh . K_bh)/8, masked. Q/K are [4096,768] with
// per-head column offset (stride DM). NT gemm, Kdim=64.
// ============================================================
__global__ __launch_bounds__(256) void scores_kernel(
    const float* __restrict__ Q, const float* __restrict__ K,
    const unsigned char* __restrict__ mask, float* __restrict__ P)
{
    int bh = blockIdx.z;
    int b = bh / NH, h = bh % NH;
    int bq = blockIdx.y * 128, bk = blockIdx.x * 128;
    const float* Qb = Q + (size_t)(b * SEQ) * DM + h * DK;
    const float* Kb = K + (size_t)(b * SEQ) * DM + h * DK;

    __shared__ float Qs[32][128];
    __shared__ float Ks[32][128];

    int tid = threadIdx.x;
    int tx = tid & 15, ty = tid >> 4;
    int mo = ty * 8, no = tx * 8;
    int lrow = tid >> 1, lc = (tid & 1) * 16;  // 2 threads/row, 16 floats each

    float acc[8][8];
#pragma unroll
    for (int i = 0; i < 8; i++)
#pragma unroll
        for (int j = 0; j < 8; j++) acc[i][j] = 0.f;

    for (int k0 = 0; k0 < DK; k0 += 32) {
        float4 qv[4], kv[4];
        const float* qp = Qb + (size_t)(bq + lrow) * DM + k0 + lc;
        const float* kp = Kb + (size_t)(bk + lrow) * DM + k0 + lc;
#pragma unroll
        for (int i = 0; i < 4; i++) {
            qv[i] = *(const float4*)(qp + i * 4);
            kv[i] = *(const float4*)(kp + i * 4);
        }
        __syncthreads();
#pragma unroll
        for (int i = 0; i < 4; i++) {
            const float* q4 = (const float*)&qv[i];
            const float* k4 = (const float*)&kv[i];
#pragma unroll
            for (int j = 0; j < 4; j++) {
                Qs[lc + i * 4 + j][lrow] = q4[j];
                Ks[lc + i * 4 + j][lrow] = k4[j];
            }
        }
        __syncthreads();
#pragma unroll
        for (int kk = 0; kk < 32; kk++) {
            float a[8], bb[8];
            *(float4*)&a[0]  = *(const float4*)&Qs[kk][mo];
            *(float4*)&a[4]  = *(const float4*)&Qs[kk][mo + 4];
            *(float4*)&bb[0] = *(const float4*)&Ks[kk][no];
            *(float4*)&bb[4] = *(const float4*)&Ks[kk][no + 4];
#pragma unroll
            for (int i = 0; i < 8; i++)
#pragma unroll
                for (int j = 0; j < 8; j++)
                    acc[i][j] += a[i] * bb[j];
        }
        __syncthreads();
    }

    const unsigned char* mrow = mask + (size_t)b * SEQ * SEQ;
    float* Pb = P + (size_t)bh * SEQ * SEQ;
#pragma unroll
    for (int i = 0; i < 8; i++) {
        int q = bq + mo + i;
#pragma unroll
        for (int j = 0; j < 8; j++) {
            int kk = bk + no + j;
            float v = acc[i][j] * 0.125f;
            if (mrow[(size_t)q * SEQ + kk]) v = -1e9f;
            Pb[(size_t)q * SEQ + kk] = v;
        }
    }
}

// ============================================================
// Row softmax over SEQ=2048, in place. 128 threads, 16 elems/thread in regs.
// ============================================================
__global__ __launch_bounds__(128) void softmax_kernel(float* __restrict__ P)
{
    size_t row = blockIdx.x;
    float* p = P + row * (size_t)SEQ;
    int tid = threadIdx.x;
    int lane = tid & 31, warp = tid >> 5;
    __shared__ float sred[4];

    float v[16];
    float m = -1e30f;
#pragma unroll
    for (int i = 0; i < 16; i++) {
        v[i] = p[tid + i * 128];
        m = fmaxf(m, v[i]);
    }
#pragma unroll
    for (int o = 16; o > 0; o >>= 1) m = fmaxf(m, __shfl_xor_sync(0xffffffffu, m, o));
    if (lane == 0) sred[warp] = m;
    __syncthreads();
    m = fmaxf(fmaxf(sred[0], sred[1]), fmaxf(sred[2], sred[3]));
    __syncthreads();

    float s = 0.f;
#pragma unroll
    for (int i = 0; i < 16; i++) {
        v[i] = __expf(v[i] - m);
        s += v[i];
    }
#pragma unroll
    for (int o = 16; o > 0; o >>= 1) s += __shfl_xor_sync(0xffffffffu, s, o);
    if (lane == 0) sred[warp] = s;
    __syncthreads();
    s = sred[0] + sred[1] + sred[2] + sred[3];
    float inv = 1.f / s;
#pragma unroll
    for (int i = 0; i < 16; i++) p[tid + i * 128] = v[i] * inv;
}

// ============================================================
// Context: ctx[b,s, h*64+d] = sum_k P[bh,s,k] * V[b*SEQ+k, h*64+d]
// Tile 128(q) x 64(d), BK=32.
// ============================================================
__global__ __launch_bounds__(256) void pv_kernel(
    const float* __restrict__ P, const float* __restrict__ V,
    float* __restrict__ ctx)
{
    int bh = blockIdx.y;
    int b = bh / NH, h = bh % NH;
    int bm = blockIdx.x * 128;
    const float* Pb = P + (size_t)bh * SEQ * SEQ;
    const float* Vb = V + (size_t)(b * SEQ) * DM + h * DK;

    __shared__ float Ps[32][128];   // [k][m]
    __shared__ float Vs[32][64];    // [k][n]

    int tid = threadIdx.x;
    int tx = tid & 15, ty = tid >> 4;
    int mo = ty * 8, no = tx * 4;
    int prow = tid >> 1, pc = (tid & 1) * 16;
    int vrow = tid >> 3, vc = (tid & 7) * 8;

    float acc[8][4];
#pragma unroll
    for (int i = 0; i < 8; i++)
#pragma unroll
        for (int j = 0; j < 4; j++) acc[i][j] = 0.f;

    for (int k0 = 0; k0 < SEQ; k0 += 32) {
        float4 pv[4], vv[2];
        const float* pp = Pb + (size_t)(bm + prow) * SEQ + k0 + pc;
        const float* vp = Vb + (size_t)(k0 + vrow) * DM + vc;
#pragma unroll
        for (int i = 0; i < 4; i++) pv[i] = *(const float4*)(pp + i * 4);
        vv[0] = *(const float4*)(vp);
        vv[1] = *(const float4*)(vp + 4);
        __syncthreads();
#pragma unroll
        for (int i = 0; i < 4; i++) {
            const float* p4 = (const float*)&pv[i];
#pragma unroll
            for (int j = 0; j < 4; j++) Ps[pc + i * 4 + j][prow] = p4[j];
        }
        *(float4*)&Vs[vrow][vc]     = vv[0];
        *(float4*)&Vs[vrow][vc + 4] = vv[1];
        __syncthreads();
#pragma unroll
        for (int kk = 0; kk < 32; kk++) {
            float a[8], bb[4];
            *(float4*)&a[0]  = *(const float4*)&Ps[kk][mo];
            *(float4*)&a[4]  = *(const float4*)&Ps[kk][mo + 4];
            *(float4*)&bb[0] = *(const float4*)&Vs[kk][no];
#pragma unroll
            for (int i = 0; i < 8; i++)
#pragma unroll
                for (int j = 0; j < 4; j++)
                    acc[i][j] += a[i] * bb[j];
        }
        __syncthreads();
    }

#pragma unroll
    for (int i = 0; i < 8; i++) {
        size_t rbase = (size_t)(b * SEQ + bm + mo + i) * DM + h * DK + no;
#pragma unroll
        for (int j = 0; j < 4; j++) ctx[rbase + j] = acc[i][j];
    }
}

// ============================================================
// LayerNorm over last dim (768). One block/row, 256 threads.
// ============================================================
__global__ __launch_bounds__(256) void layernorm_kernel(
    const float* __restrict__ X, const float* __restrict__ gam,
    const float* __restrict__ bet, float* __restrict__ Y)
{
    int row = blockIdx.x;
    const float* x = X + (size_t)row * DM;
    float* y = Y + (size_t)row * DM;
    int tid = threadIdx.x;
    int lane = tid & 31, warp = tid >> 5;
    __shared__ float sw[8];

    float v0 = x[tid], v1 = x[tid + 256], v2 = x[tid + 512];
    float s = v0 + v1 + v2;
#pragma unroll
    for (int o = 16; o > 0; o >>= 1) s += __shfl_xor_sync(0xffffffffu, s, o);
    if (lane == 0) sw[warp] = s;
    __syncthreads();
    s = 0.f;
#pragma unroll
    for (int w = 0; w < 8; w++) s += sw[w];
    float mean = s * (1.f / 768.f);
    __syncthreads();

    float d0 = v0 - mean, d1 = v1 - mean, d2 = v2 - mean;
    float sq = d0 * d0 + d1 * d1 + d2 * d2;
#pragma unroll
    for (int o = 16; o > 0; o >>= 1) sq += __shfl_xor_sync(0xffffffffu, sq, o);
    if (lane == 0) sw[warp] = sq;
    __syncthreads();
    sq = 0.f;
#pragma unroll
    for (int w = 0; w < 8; w++) sq += sw[w];
    float var = sq * (1.f / 768.f);
    float rstd = rsqrtf(var + 1e-5f);

    y[tid]       = d0 * rstd * gam[tid]       + bet[tid];
    y[tid + 256] = d1 * rstd * gam[tid + 256] + bet[tid + 256];
    y[tid + 512] = d2 * rstd * gam[tid + 512] + bet[tid + 512];
}

// ============================================================
extern "C" void kernel_launch(void* const* d_in, const int* in_sizes, int n_in,
                              void* d_out, int out_size)
{
    const float* x    = (const float*)d_in[0];
    const unsigned char* mask = (const unsigned char*)d_in[1];
    const float* Wq = (const float*)d_in[2];
    const float* bq = (const float*)d_in[3];
    const float* Wk = (const float*)d_in[4];
    const float* bk = (const float*)d_in[5];
    const float* Wv = (const float*)d_in[6];
    const float* bv = (const float*)d_in[7];
    const float* Wo = (const float*)d_in[8];
    const float* bo = (const float*)d_in[9];
    const float* ln1g = (const float*)d_in[10];
    const float* ln1b = (const float*)d_in[11];
    const float* W1 = (const float*)d_in[12];
    const float* b1 = (const float*)d_in[13];
    const float* W2 = (const float*)d_in[14];
    const float* b2 = (const float*)d_in[15];
    const float* ln2g = (const float*)d_in[16];
    const float* ln2b = (const float*)d_in[17];
    float* out = (float*)d_out;

    float *Q, *K, *V, *Pd, *ctx, *t0, *ao, *h, *f;
    cudaGetSymbolAddress((void**)&Q,   g_Q);
    cudaGetSymbolAddress((void**)&K,   g_K);
    cudaGetSymbolAddress((void**)&V,   g_V);
    cudaGetSymbolAddress((void**)&Pd,  g_P);
    cudaGetSymbolAddress((void**)&ctx, g_ctx);
    cudaGetSymbolAddress((void**)&t0,  g_t0);
    cudaGetSymbolAddress((void**)&ao,  g_ao);
    cudaGetSymbolAddress((void**)&h,   g_h);
    cudaGetSymbolAddress((void**)&f,   g_f);

    // attn is the 2nd output; write it directly into d_out when present
    float* Pbuf = ((size_t)out_size >= (size_t)OUT_ELEMS + ATT_ELEMS)
                ? (out + OUT_ELEMS) : Pd;

    dim3 g768(DM / 128, MROWS / 128);
    sgemm128<false><<<g768, 256>>>(x, Wq, bq, nullptr, Q, MROWS, DM, DM);
    sgemm128<false><<<g768, 256>>>(x, Wk, bk, nullptr, K, MROWS, DM, DM);
    sgemm128<false><<<g768, 256>>>(x, Wv, bv, nullptr, V, MROWS, DM, DM);

    dim3 gs(SEQ / 128, SEQ / 128, BHN);
    scores_kernel<<<gs, 256>>>(Q, K, mask, Pbuf);
    softmax_kernel<<<BHN * SEQ, 128>>>(Pbuf);

    dim3 gpv(SEQ / 128, BHN);
    pv_kernel<<<gpv, 256>>>(Pbuf, V, ctx);

    sgemm128<false><<<g768, 256>>>(ctx, Wo, bo, x, t0, MROWS, DM, DM);
    layernorm_kernel<<<MROWS, 256>>>(t0, ln1g, ln1b, ao);

    dim3 gff1(DFF / 128, MROWS / 128);
    sgemm128<true><<<gff1, 256>>>(ao, W1, b1, nullptr, h, MROWS, DFF, DM);
    sgemm128<false><<<g768, 256>>>(h, W2, b2, ao, f, MROWS, DM, DFF);
    layernorm_kernel<<<MROWS, 256>>>(f, ln2g, ln2b, out);
}

// round 5
// speedup vs baseline: 2.0222x; 2.0222x over previous
#include <cuda_runtime.h>
#include <cuda_fp16.h>
#include <math.h>
#include <stdint.h>

#define DM 768
#define DFF 3072
#define NH 12
#define DK 64
#define BATCH 2
#define SEQ 2048
#define MROWS (BATCH*SEQ)            // 4096
#define BHN (BATCH*NH)               // 24
#define OUT_ELEMS (MROWS*DM)         // 3145728
#define ATT_ELEMS ((size_t)BHN*SEQ*SEQ) // 100663296

// ---- scratch (allocation-free: __device__ globals) ----
__device__ __align__(16) __half g_Qh[MROWS*DM];
__device__ __align__(16) __half g_Kh[MROWS*DM];
__device__ __align__(16) __half g_Vh[MROWS*DM];
__device__ __align__(16) float g_P[BHN*(size_t)SEQ*SEQ]; // fallback if attn not in d_out
__device__ __align__(16) float g_ctx[MROWS*DM];
__device__ __align__(16) float g_t0[MROWS*DM];
__device__ __align__(16) float g_ao[MROWS*DM];
__device__ __align__(16) float g_h[MROWS*DFF];
__device__ __align__(16) float g_f[MROWS*DM];

__device__ __forceinline__ uint32_t pack_h2(float x, float y) {
    __half2 h = __floats2half2_rn(x, y);
    return *(uint32_t*)&h;
}

__device__ __forceinline__ void mma16816(float* c, const uint32_t* a, const uint32_t* b) {
    asm volatile(
        "mma.sync.aligned.m16n8k16.row.col.f32.f16.f16.f32 "
        "{%0,%1,%2,%3}, {%4,%5,%6,%7}, {%8,%9}, {%0,%1,%2,%3};"
        : "+f"(c[0]), "+f"(c[1]), "+f"(c[2]), "+f"(c[3])
        : "r"(a[0]), "r"(a[1]), "r"(a[2]), "r"(a[3]), "r"(b[0]), "r"(b[1]));
}

// ============================================================
// Dense GEMM: C[M,N] = A[M,K](f32) @ W[K,N](f32) + bias (+resid)(+relu)
// Block 128x128, BK=32, 8 warps (warp tile 32x64), mma.sync f16.
// As: half [m(128)][k] pitch 40 halves.  Bs: packed k-pair words [k2(16)][n(128)] pitch 132.
// ============================================================
#define APITCH 40
#define BPITCH 132

template<int RELU, int OUTHALF>
__global__ __launch_bounds__(256) void mma_gemm(
    const float* __restrict__ A, const float* __restrict__ W,
    const float* __restrict__ bias, const float* __restrict__ resid,
    float* __restrict__ C, __half* __restrict__ Ch,
    int M, int N, int K)
{
    __shared__ __half As[2][128*APITCH];
    __shared__ uint32_t Bs[2][16*BPITCH];

    int tid = threadIdx.x, lane = tid & 31, warp = tid >> 5;
    int wm = warp >> 1, wn = warp & 1;
    int g = lane >> 2, tg = lane & 3;
    int bm = blockIdx.y * 128, bn = blockIdx.x * 128;
    int m_l = tid & 127, ks = (tid >> 7) * 16;

    float acc[2][8][4];
#pragma unroll
    for (int mt = 0; mt < 2; mt++)
#pragma unroll
        for (int nt = 0; nt < 8; nt++)
#pragma unroll
            for (int q = 0; q < 4; q++) acc[mt][nt][q] = 0.f;

    const int NC = K / 32;
    float ar[16], br[16];

#define GL(k0) { \
    const float* Ap = A + (size_t)(bm + m_l) * K + (k0) + ks; \
    _Pragma("unroll") \
    for (int q = 0; q < 4; q++) *(float4*)&ar[q*4] = *(const float4*)(Ap + q*4); \
    const float* Wp = W + (size_t)((k0) + ks) * N + bn + m_l; \
    _Pragma("unroll") \
    for (int j = 0; j < 16; j++) br[j] = Wp[(size_t)j * N]; }

#define ST(buf) { \
    uint32_t pk[8]; \
    _Pragma("unroll") \
    for (int q = 0; q < 8; q++) pk[q] = pack_h2(ar[2*q], ar[2*q+1]); \
    uint4* dst = (uint4*)(&As[buf][m_l*APITCH + ks]); \
    dst[0] = make_uint4(pk[0],pk[1],pk[2],pk[3]); \
    dst[1] = make_uint4(pk[4],pk[5],pk[6],pk[7]); \
    _Pragma("unroll") \
    for (int j = 0; j < 8; j++) \
        Bs[buf][((ks>>1) + j)*BPITCH + m_l] = pack_h2(br[2*j], br[2*j+1]); }

    GL(0); ST(0);
    __syncthreads();

    for (int i = 0; i < NC; i++) {
        int buf = i & 1;
        if (i + 1 < NC) GL((i + 1) * 32);
#pragma unroll
        for (int ks16 = 0; ks16 < 32; ks16 += 16) {
            uint32_t a[2][4];
#pragma unroll
            for (int mt = 0; mt < 2; mt++) {
                int r = wm * 32 + mt * 16 + g;
                const __half* ab = &As[buf][0];
                a[mt][0] = *(const uint32_t*)(ab + r*APITCH + ks16 + tg*2);
                a[mt][1] = *(const uint32_t*)(ab + (r+8)*APITCH + ks16 + tg*2);
                a[mt][2] = *(const uint32_t*)(ab + r*APITCH + ks16 + 8 + tg*2);
                a[mt][3] = *(const uint32_t*)(ab + (r+8)*APITCH + ks16 + 8 + tg*2);
            }
#pragma unroll
            for (int nt = 0; nt < 8; nt++) {
                int cn = wn * 64 + nt * 8 + g;
                uint32_t b[2];
                b[0] = Bs[buf][((ks16>>1) + tg) * BPITCH + cn];
                b[1] = Bs[buf][((ks16>>1) + tg + 4) * BPITCH + cn];
#pragma unroll
                for (int mt = 0; mt < 2; mt++) mma16816(acc[mt][nt], a[mt], b);
            }
        }
        if (i + 1 < NC) ST(1 - buf);
        __syncthreads();
    }
#undef GL
#undef ST

#pragma unroll
    for (int mt = 0; mt < 2; mt++) {
#pragma unroll
        for (int nt = 0; nt < 8; nt++) {
            int c = bn + wn * 64 + nt * 8 + tg * 2;
            float bx = bias[c], by = bias[c + 1];
#pragma unroll
            for (int hh = 0; hh < 2; hh++) {
                int r = bm + wm * 32 + mt * 16 + g + hh * 8;
                float v0 = acc[mt][nt][hh*2+0] + bx;
                float v1 = acc[mt][nt][hh*2+1] + by;
                if (resid) {
                    float2 rv = *(const float2*)(resid + (size_t)r * N + c);
                    v0 += rv.x; v1 += rv.y;
                }
                if (RELU) { v0 = fmaxf(v0, 0.f); v1 = fmaxf(v1, 0.f); }
                if (OUTHALF)
                    *(__half2*)(Ch + (size_t)r * N + c) = __floats2half2_rn(v0, v1);
                else
                    *(float2*)(C + (size_t)r * N + c) = make_float2(v0, v1);
            }
        }
    }
}

// ============================================================
// Scores: P[bh,q,k] = (Q.K)/8 masked.  Qh/Kh fp16 [4096,768], head col offset.
// Block 128q x 128k, whole d=64 in smem, 4 k16 mma steps.
// ============================================================
#define SPITCH 72

__global__ __launch_bounds__(256) void scores_mma(
    const __half* __restrict__ Qh, const __half* __restrict__ Kh,
    const unsigned char* __restrict__ mask, float* __restrict__ P)
{
    __shared__ __half Qs[128*SPITCH];
    __shared__ __half Ks[128*SPITCH];

    int bh = blockIdx.z, b = bh / NH, h = bh % NH;
    int bq = blockIdx.y * 128, bk = blockIdx.x * 128;
    const __half* Qb = Qh + (size_t)(b * SEQ) * DM + h * DK;
    const __half* Kb = Kh + (size_t)(b * SEQ) * DM + h * DK;

    int tid = threadIdx.x, lane = tid & 31, warp = tid >> 5;
    int wm = warp >> 1, wn = warp & 1;
    int g = lane >> 2, tg = lane & 3;
    int m_l = tid & 127, part = tid >> 7;

    {
        const uint4* qp = (const uint4*)(Qb + (size_t)(bq + m_l) * DM + part * 32);
        const uint4* kp = (const uint4*)(Kb + (size_t)(bk + m_l) * DM + part * 32);
        uint4* qd = (uint4*)(Qs + m_l * SPITCH + part * 32);
        uint4* kd = (uint4*)(Ks + m_l * SPITCH + part * 32);
#pragma unroll
        for (int j = 0; j < 4; j++) { qd[j] = qp[j]; kd[j] = kp[j]; }
    }
    __syncthreads();

    float acc[2][8][4];
#pragma unroll
    for (int mt = 0; mt < 2; mt++)
#pragma unroll
        for (int nt = 0; nt < 8; nt++)
#pragma unroll
            for (int q = 0; q < 4; q++) acc[mt][nt][q] = 0.f;

#pragma unroll
    for (int ks16 = 0; ks16 < 64; ks16 += 16) {
        uint32_t a[2][4];
#pragma unroll
        for (int mt = 0; mt < 2; mt++) {
            int r = wm * 32 + mt * 16 + g;
            a[mt][0] = *(const uint32_t*)(Qs + r*SPITCH + ks16 + tg*2);
            a[mt][1] = *(const uint32_t*)(Qs + (r+8)*SPITCH + ks16 + tg*2);
            a[mt][2] = *(const uint32_t*)(Qs + r*SPITCH + ks16 + 8 + tg*2);
            a[mt][3] = *(const uint32_t*)(Qs + (r+8)*SPITCH + ks16 + 8 + tg*2);
        }
#pragma unroll
        for (int nt = 0; nt < 8; nt++) {
            int cn = wn * 64 + nt * 8 + g;
            uint32_t bfr[2];
            bfr[0] = *(const uint32_t*)(Ks + cn*SPITCH + ks16 + tg*2);
            bfr[1] = *(const uint32_t*)(Ks + cn*SPITCH + ks16 + 8 + tg*2);
#pragma unroll
            for (int mt = 0; mt < 2; mt++) mma16816(acc[mt][nt], a[mt], bfr);
        }
    }

    const unsigned char* mrow = mask + (size_t)b * SEQ * SEQ;
    float* Pb = P + (size_t)bh * SEQ * SEQ;
#pragma unroll
    for (int mt = 0; mt < 2; mt++) {
#pragma unroll
        for (int nt = 0; nt < 8; nt++) {
            int c = bk + wn * 64 + nt * 8 + tg * 2;
#pragma unroll
            for (int hh = 0; hh < 2; hh++) {
                int q = bq + wm * 32 + mt * 16 + g + hh * 8;
                float v0 = acc[mt][nt][hh*2+0] * 0.125f;
                float v1 = acc[mt][nt][hh*2+1] * 0.125f;
                if (mrow[(size_t)q * SEQ + c])     v0 = -1e9f;
                if (mrow[(size_t)q * SEQ + c + 1]) v1 = -1e9f;
                *(float2*)(Pb + (size_t)q * SEQ + c) = make_float2(v0, v1);
            }
        }
    }
}

// ============================================================
// Row softmax over SEQ=2048, in place.
// ============================================================
__global__ __launch_bounds__(128) void softmax_kernel(float* __restrict__ P)
{
    size_t row = blockIdx.x;
    float* p = P + row * (size_t)SEQ;
    int tid = threadIdx.x;
    int lane = tid & 31, warp = tid >> 5;
    __shared__ float sred[4];

    float v[16];
    float m = -1e30f;
#pragma unroll
    for (int i = 0; i < 16; i++) {
        v[i] = p[tid + i * 128];
        m = fmaxf(m, v[i]);
    }
#pragma unroll
    for (int o = 16; o > 0; o >>= 1) m = fmaxf(m, __shfl_xor_sync(0xffffffffu, m, o));
    if (lane == 0) sred[warp] = m;
    __syncthreads();
    m = fmaxf(fmaxf(sred[0], sred[1]), fmaxf(sred[2], sred[3]));
    __syncthreads();

    float s = 0.f;
#pragma unroll
    for (int i = 0; i < 16; i++) {
        v[i] = __expf(v[i] - m);
        s += v[i];
    }
#pragma unroll
    for (int o = 16; o > 0; o >>= 1) s += __shfl_xor_sync(0xffffffffu, s, o);
    if (lane == 0) sred[warp] = s;
    __syncthreads();
    s = sred[0] + sred[1] + sred[2] + sred[3];
    float inv = 1.f / s;
#pragma unroll
    for (int i = 0; i < 16; i++) p[tid + i * 128] = v[i] * inv;
}

// ============================================================
// PV: ctx[b,s,h*64+d] = sum_k P[bh,s,k] * V[k,h*64+d]
// Block 128q x 64d, BK=32, double-buffered, mma.sync f16.
// Ps: half [m(128)][k] pitch 40.  Vs: packed k-pair words [k2(16)][d(64)] pitch 68.
// ============================================================
#define VPITCH 68

__global__ __launch_bounds__(256) void pv_mma(
    const float* __restrict__ P, const __half* __restrict__ Vh,
    float* __restrict__ ctx)
{
    __shared__ __half Ps[2][128*APITCH];
    __shared__ uint32_t Vs[2][16*VPITCH];

    int bh = blockIdx.y, b = bh / NH, h = bh % NH;
    int bm = blockIdx.x * 128;
    const float* Pb = P + (size_t)bh * SEQ * SEQ;
    const __half* Vb = Vh + (size_t)(b * SEQ) * DM + h * DK;

    int tid = threadIdx.x, lane = tid & 31, warp = tid >> 5;
    int wm = warp >> 1, wn = warp & 1;
    int g = lane >> 2, tg = lane & 3;
    int m_l = tid & 127, ks = (tid >> 7) * 16;
    int d_l = tid & 63, k2b = (tid >> 6);   // k2 = k2b*... (4 groups x 4 iters)

    float acc[2][4][4];
#pragma unroll
    for (int mt = 0; mt < 2; mt++)
#pragma unroll
        for (int nt = 0; nt < 4; nt++)
#pragma unroll
            for (int q = 0; q < 4; q++) acc[mt][nt][q] = 0.f;

    float pr[16];
    __half v0r[4], v1r[4];

#define GLPV(k0) { \
    const float* pp = Pb + (size_t)(bm + m_l) * SEQ + (k0) + ks; \
    _Pragma("unroll") \
    for (int q = 0; q < 4; q++) *(float4*)&pr[q*4] = *(const float4*)(pp + q*4); \
    _Pragma("unroll") \
    for (int j = 0; j < 4; j++) { \
        int k2 = k2b * 4 + j; \
        v0r[j] = Vb[(size_t)((k0) + 2*k2) * DM + d_l]; \
        v1r[j] = Vb[(size_t)((k0) + 2*k2 + 1) * DM + d_l]; } }

#define STPV(buf) { \
    uint32_t pk[8]; \
    _Pragma("unroll") \
    for (int q = 0; q < 8; q++) pk[q] = pack_h2(pr[2*q], pr[2*q+1]); \
    uint4* dst = (uint4*)(&Ps[buf][m_l*APITCH + ks]); \
    dst[0] = make_uint4(pk[0],pk[1],pk[2],pk[3]); \
    dst[1] = make_uint4(pk[4],pk[5],pk[6],pk[7]); \
    _Pragma("unroll") \
    for (int j = 0; j < 4; j++) { \
        int k2 = k2b * 4 + j; \
        __half2 hv; hv.x = v0r[j]; hv.y = v1r[j]; \
        Vs[buf][k2 * VPITCH + d_l] = *(uint32_t*)&hv; } }

    GLPV(0); STPV(0);
    __syncthreads();

    const int NC = SEQ / 32;
    for (int i = 0; i < NC; i++) {
        int buf = i & 1;
        if (i + 1 < NC) GLPV((i + 1) * 32);
#pragma unroll
        for (int ks16 = 0; ks16 < 32; ks16 += 16) {
            uint32_t a[2][4];
#pragma unroll
            for (int mt = 0; mt < 2; mt++) {
                int r = wm * 32 + mt * 16 + g;
                const __half* ab = &Ps[buf][0];
                a[mt][0] = *(const uint32_t*)(ab + r*APITCH + ks16 + tg*2);
                a[mt][1] = *(const uint32_t*)(ab + (r+8)*APITCH + ks16 + tg*2);
                a[mt][2] = *(const uint32_t*)(ab + r*APITCH + ks16 + 8 + tg*2);
                a[mt][3] = *(const uint32_t*)(ab + (r+8)*APITCH + ks16 + 8 + tg*2);
            }
#pragma unroll
            for (int nt = 0; nt < 4; nt++) {
                int dn = wn * 32 + nt * 8 + g;
                uint32_t bfr[2];
                bfr[0] = Vs[buf][((ks16>>1) + tg) * VPITCH + dn];
                bfr[1] = Vs[buf][((ks16>>1) + tg + 4) * VPITCH + dn];
#pragma unroll
                for (int mt = 0; mt < 2; mt++) mma16816(acc[mt][nt], a[mt], bfr);
            }
        }
        if (i + 1 < NC) STPV(1 - buf);
        __syncthreads();
    }
#undef GLPV
#undef STPV

#pragma unroll
    for (int mt = 0; mt < 2; mt++) {
#pragma unroll
        for (int nt = 0; nt < 4; nt++) {
            int cn = wn * 32 + nt * 8 + tg * 2;
#pragma unroll
            for (int hh = 0; hh < 2; hh++) {
                int r = bm + wm * 32 + mt * 16 + g + hh * 8;
                *(float2*)(ctx + (size_t)(b * SEQ + r) * DM + h * DK + cn) =
                    make_float2(acc[mt][nt][hh*2+0], acc[mt][nt][hh*2+1]);
            }
        }
    }
}

// ============================================================
// LayerNorm over last dim (768).
// ============================================================
__global__ __launch_bounds__(256) void layernorm_kernel(
    const float* __restrict__ X, const float* __restrict__ gam,
    const float* __restrict__ bet, float* __restrict__ Y)
{
    int row = blockIdx.x;
    const float* x = X + (size_t)row * DM;
    float* y = Y + (size_t)row * DM;
    int tid = threadIdx.x;
    int lane = tid & 31, warp = tid >> 5;
    __shared__ float sw[8];

    float v0 = x[tid], v1 = x[tid + 256], v2 = x[tid + 512];
    float s = v0 + v1 + v2;
#pragma unroll
    for (int o = 16; o > 0; o >>= 1) s += __shfl_xor_sync(0xffffffffu, s, o);
    if (lane == 0) sw[warp] = s;
    __syncthreads();
    s = 0.f;
#pragma unroll
    for (int w = 0; w < 8; w++) s += sw[w];
    float mean = s * (1.f / 768.f);
    __syncthreads();

    float d0 = v0 - mean, d1 = v1 - mean, d2 = v2 - mean;
    float sq = d0 * d0 + d1 * d1 + d2 * d2;
#pragma unroll
    for (int o = 16; o > 0; o >>= 1) sq += __shfl_xor_sync(0xffffffffu, sq, o);
    if (lane == 0) sw[warp] = sq;
    __syncthreads();
    sq = 0.f;
#pragma unroll
    for (int w = 0; w < 8; w++) sq += sw[w];
    float var = sq * (1.f / 768.f);
    float rstd = rsqrtf(var + 1e-5f);

    y[tid]       = d0 * rstd * gam[tid]       + bet[tid];
    y[tid + 256] = d1 * rstd * gam[tid + 256] + bet[tid + 256];
    y[tid + 512] = d2 * rstd * gam[tid + 512] + bet[tid + 512];
}

// ============================================================
extern "C" void kernel_launch(void* const* d_in, const int* in_sizes, int n_in,
                              void* d_out, int out_size)
{
    const float* x    = (const float*)d_in[0];
    const unsigned char* mask = (const unsigned char*)d_in[1];
    const float* Wq = (const float*)d_in[2];
    const float* bq = (const float*)d_in[3];
    const float* Wk = (const float*)d_in[4];
    const float* bk = (const float*)d_in[5];
    const float* Wv = (const float*)d_in[6];
    const float* bv = (const float*)d_in[7];
    const float* Wo = (const float*)d_in[8];
    const float* bo = (const float*)d_in[9];
    const float* ln1g = (const float*)d_in[10];
    const float* ln1b = (const float*)d_in[11];
    const float* W1 = (const float*)d_in[12];
    const float* b1 = (const float*)d_in[13];
    const float* W2 = (const float*)d_in[14];
    const float* b2 = (const float*)d_in[15];
    const float* ln2g = (const float*)d_in[16];
    const float* ln2b = (const float*)d_in[17];
    float* out = (float*)d_out;

    __half *Qh, *Kh, *Vh;
    float *Pd, *ctx, *t0, *ao, *h, *f;
    cudaGetSymbolAddress((void**)&Qh,  g_Qh);
    cudaGetSymbolAddress((void**)&Kh,  g_Kh);
    cudaGetSymbolAddress((void**)&Vh,  g_Vh);
    cudaGetSymbolAddress((void**)&Pd,  g_P);
    cudaGetSymbolAddress((void**)&ctx, g_ctx);
    cudaGetSymbolAddress((void**)&t0,  g_t0);
    cudaGetSymbolAddress((void**)&ao,  g_ao);
    cudaGetSymbolAddress((void**)&h,   g_h);
    cudaGetSymbolAddress((void**)&f,   g_f);

    // attn is the 2nd output; write it directly into d_out when present
    float* Pbuf = ((size_t)out_size >= (size_t)OUT_ELEMS + ATT_ELEMS)
                ? (out + OUT_ELEMS) : Pd;

    dim3 g768(DM / 128, MROWS / 128);
    mma_gemm<0,1><<<g768, 256>>>(x, Wq, bq, nullptr, nullptr, Qh, MROWS, DM, DM);
    mma_gemm<0,1><<<g768, 256>>>(x, Wk, bk, nullptr, nullptr, Kh, MROWS, DM, DM);
    mma_gemm<0,1><<<g768, 256>>>(x, Wv, bv, nullptr, nullptr, Vh, MROWS, DM, DM);

    dim3 gs(SEQ / 128, SEQ / 128, BHN);
    scores_mma<<<gs, 256>>>(Qh, Kh, mask, Pbuf);
    softmax_kernel<<<BHN * SEQ, 128>>>(Pbuf);

    dim3 gpv(SEQ / 128, BHN);
    pv_mma<<<gpv, 256>>>(Pbuf, Vh, ctx);

    mma_gemm<0,0><<<g768, 256>>>(ctx, Wo, bo, x, t0, nullptr, MROWS, DM, DM);
    layernorm_kernel<<<MROWS, 256>>>(t0, ln1g, ln1b, ao);

    dim3 gff1(DFF / 128, MROWS / 128);
    mma_gemm<1,0><<<gff1, 256>>>(ao, W1, b1, nullptr, h, nullptr, MROWS, DFF, DM);
    mma_gemm<0,0><<<g768, 256>>>(h, W2, b2, ao, f, nullptr, MROWS, DM, DFF);
    layernorm_kernel<<<MROWS, 256>>>(f, ln2g, ln2b, out);
}

// round 10
// speedup vs baseline: 3.2573x; 1.6107x over previous
#include <cuda_runtime.h>
#include <cuda_fp16.h>
#include <math.h>
#include <stdint.h>

#define DM 768
#define DFF 3072
#define NH 12
#define DK 64
#define BATCH 2
#define SEQ 2048
#define MROWS (BATCH*SEQ)            // 4096
#define BHN (BATCH*NH)               // 24
#define OUT_ELEMS (MROWS*DM)
#define ATT_ELEMS ((size_t)BHN*SEQ*SEQ)

// ---- scratch (allocation-free: __device__ globals) ----
__device__ __align__(16) __half g_xh [MROWS*DM];
__device__ __align__(16) __half g_Wqh[DM*DM];
__device__ __align__(16) __half g_Wkh[DM*DM];
__device__ __align__(16) __half g_Wvh[DM*DM];
__device__ __align__(16) __half g_Woh[DM*DM];
__device__ __align__(16) __half g_W1h[DM*DFF];
__device__ __align__(16) __half g_W2h[DFF*DM];
__device__ __align__(16) __half g_Qh [MROWS*DM];
__device__ __align__(16) __half g_Kh [MROWS*DM];
__device__ __align__(16) __half g_Vh [MROWS*DM];
__device__ __align__(16) __half g_ctxh[MROWS*DM];
__device__ __align__(16) __half g_aoh[MROWS*DM];
__device__ __align__(16) __half g_hh [MROWS*DFF];
__device__ __align__(16) float g_P[BHN*(size_t)SEQ*SEQ];
__device__ __align__(16) float g_t0[MROWS*DM];
__device__ __align__(16) float g_ao[MROWS*DM];
__device__ __align__(16) float g_f [MROWS*DM];

__device__ __forceinline__ uint32_t smem_u32(const void* p) {
    uint32_t a;
    asm("{ .reg .u64 t; cvta.to.shared.u64 t, %1; cvt.u32.u64 %0, t; }"
        : "=r"(a) : "l"(p));
    return a;
}

__device__ __forceinline__ uint32_t pack_h2(float x, float y) {
    __half2 h = __floats2half2_rn(x, y);
    return *(uint32_t*)&h;
}

__device__ __forceinline__ void mma16816(float* c, const uint32_t* a, const uint32_t* b) {
    asm volatile(
        "mma.sync.aligned.m16n8k16.row.col.f32.f16.f16.f32 "
        "{%0,%1,%2,%3}, {%4,%5,%6,%7}, {%8,%9}, {%0,%1,%2,%3};"
        : "+f"(c[0]), "+f"(c[1]), "+f"(c[2]), "+f"(c[3])
        : "r"(a[0]), "r"(a[1]), "r"(a[2]), "r"(a[3]), "r"(b[0]), "r"(b[1]));
}

#define LDSM_X4(r0,r1,r2,r3,addr) \
    asm volatile("ldmatrix.sync.aligned.m8n8.x4.shared.b16 {%0,%1,%2,%3}, [%4];" \
        : "=r"(r0),"=r"(r1),"=r"(r2),"=r"(r3) : "r"(addr))
#define LDSM_X4T(r0,r1,r2,r3,addr) \
    asm volatile("ldmatrix.sync.aligned.m8n8.x4.trans.shared.b16 {%0,%1,%2,%3}, [%4];" \
        : "=r"(r0),"=r"(r1),"=r"(r2),"=r"(r3) : "r"(addr))
#define CP_ASYNC16(saddr, gptr) \
    asm volatile("cp.async.cg.shared.global [%0], [%1], 16;" :: "r"(saddr), "l"(gptr))
#define CP_COMMIT() asm volatile("cp.async.commit_group;")
#define CP_WAIT1()  asm volatile("cp.async.wait_group 1;")

// ============================================================
// f32 -> f16 convert (n divisible by 1024; 4 elems/thread)
// ============================================================
__global__ __launch_bounds__(256) void f2h_kernel(
    const float* __restrict__ X, __half* __restrict__ Y)
{
    int i = (blockIdx.x * 256 + threadIdx.x) * 4;
    float4 v = *(const float4*)(X + i);
    *(__half2*)(Y + i)     = __floats2half2_rn(v.x, v.y);
    *(__half2*)(Y + i + 2) = __floats2half2_rn(v.z, v.w);
}

// ============================================================
// fp16 GEMM: C[M,N] = A[M,K](f16) @ W[K,N](f16) + bias (+resid)(+relu)
// 128x128x32, 3-stage cp.async, ldmatrix frags, 8 warps.
// smem/stage = A 8KB (128x32 halves, chunk^((r>>1)&3) swizzle)
//            + B 8KB (32x128 halves, chunk^(k&7) swizzle). 3 stages = 48KB dyn.
// ============================================================
template<int RELU, int OUTF32, int OUTHALF>
__global__ __launch_bounds__(256, 2) void hgemm(
    const __half* __restrict__ A, const __half* __restrict__ W,
    const float* __restrict__ bias, const float* __restrict__ resid,
    float* __restrict__ C, __half* __restrict__ Ch,
    int M, int N, int K)
{
    extern __shared__ char dsm[];
    uint32_t sb = smem_u32(dsm);

    int tid = threadIdx.x, lane = tid & 31, warp = tid >> 5;
    int wm = warp >> 1, wn = warp & 1;
    int g = lane >> 2, tg = lane & 3;
    int bm = blockIdx.y * 128, bn = blockIdx.x * 128;

    float acc[2][8][4];
#pragma unroll
    for (int mt = 0; mt < 2; mt++)
#pragma unroll
        for (int nt = 0; nt < 8; nt++)
#pragma unroll
            for (int q = 0; q < 4; q++) acc[mt][nt][q] = 0.f;

    const int NC = K / 32;

    // per-thread cp.async assignments
    int ar0 = tid >> 2, ac0 = tid & 3;           // + j*64 rows
    int bk0 = tid >> 4, bc0 = tid & 15;          // + j*16 k-rows

#define LOAD_STAGE(stg, k0) { \
    uint32_t base = sb + (stg) * 16384; \
    _Pragma("unroll") \
    for (int j = 0; j < 2; j++) { \
        int r = ar0 + j * 64, c = ac0; \
        uint32_t sa = base + r * 64 + ((c ^ ((r >> 1) & 3)) << 4); \
        CP_ASYNC16(sa, A + (size_t)(bm + r) * K + (k0) + c * 8); \
    } \
    _Pragma("unroll") \
    for (int j = 0; j < 2; j++) { \
        int k = bk0 + j * 16, c = bc0; \
        uint32_t sa = base + 8192 + k * 256 + ((c ^ (k & 7)) << 4); \
        CP_ASYNC16(sa, W + (size_t)((k0) + k) * N + bn + c * 8); \
    } \
    CP_COMMIT(); }

    LOAD_STAGE(0, 0);
    LOAD_STAGE(1, 32);

    int st = 0;
    for (int i = 0; i < NC; i++) {
        CP_WAIT1();
        __syncthreads();
        if (i + 2 < NC) {
            int st2 = st + 2; if (st2 >= 3) st2 -= 3;
            LOAD_STAGE(st2, (i + 2) * 32);
        } else {
            CP_COMMIT();
        }
        uint32_t base = sb + st * 16384;
#pragma unroll
        for (int kk = 0; kk < 2; kk++) {
            int ks16 = kk * 16;
            uint32_t a[2][4];
#pragma unroll
            for (int mt = 0; mt < 2; mt++) {
                int row = wm * 32 + mt * 16 + (lane & 15);
                int ch = (ks16 >> 3) + (lane >> 4);
                uint32_t ad = base + row * 64 + ((ch ^ ((row >> 1) & 3)) << 4);
                LDSM_X4(a[mt][0], a[mt][1], a[mt][2], a[mt][3], ad);
            }
#pragma unroll
            for (int p = 0; p < 4; p++) {
                int k = ks16 + (lane & 15);
                int ch = wn * 8 + p * 2 + (lane >> 4);
                uint32_t bd = base + 8192 + k * 256 + ((ch ^ (k & 7)) << 4);
                uint32_t b0, b1, b2, b3;
                LDSM_X4T(b0, b1, b2, b3, bd);
                uint32_t f0[2] = {b0, b1}, f1[2] = {b2, b3};
#pragma unroll
                for (int mt = 0; mt < 2; mt++) {
                    mma16816(acc[mt][2*p],     a[mt], f0);
                    mma16816(acc[mt][2*p + 1], a[mt], f1);
                }
            }
        }
        st++; if (st >= 3) st = 0;
    }
#undef LOAD_STAGE

#pragma unroll
    for (int mt = 0; mt < 2; mt++) {
#pragma unroll
        for (int nt = 0; nt < 8; nt++) {
            int c = bn + wn * 64 + nt * 8 + tg * 2;
            float bx = bias[c], by = bias[c + 1];
#pragma unroll
            for (int hh = 0; hh < 2; hh++) {
                int r = bm + wm * 32 + mt * 16 + g + hh * 8;
                float v0 = acc[mt][nt][hh*2+0] + bx;
                float v1 = acc[mt][nt][hh*2+1] + by;
                if (OUTF32 && resid) {
                    float2 rv = *(const float2*)(resid + (size_t)r * N + c);
                    v0 += rv.x; v1 += rv.y;
                }
                if (RELU) { v0 = fmaxf(v0, 0.f); v1 = fmaxf(v1, 0.f); }
                if (OUTF32)
                    *(float2*)(C + (size_t)r * N + c) = make_float2(v0, v1);
                if (OUTHALF)
                    *(__half2*)(Ch + (size_t)r * N + c) = __floats2half2_rn(v0, v1);
            }
        }
    }
}

// ============================================================
// Scores: P[bh,q,k] = (Q.K)/8 masked. smem-staged coalesced epilogue.
// ============================================================
#define SPITCH 72
#define STPITCH 132

__global__ __launch_bounds__(256) void scores_mma(
    const __half* __restrict__ Qh, const __half* __restrict__ Kh,
    const unsigned char* __restrict__ mask, float* __restrict__ P)
{
    __shared__ union {
        struct { __half Qs[128*SPITCH]; __half Ks[128*SPITCH]; } qk;
        float stage[64*STPITCH];
    } su;

    int bh = blockIdx.z, b = bh / NH, h = bh % NH;
    int bq = blockIdx.y * 128, bk = blockIdx.x * 128;
    const __half* Qb = Qh + (size_t)(b * SEQ) * DM + h * DK;
    const __half* Kb = Kh + (size_t)(b * SEQ) * DM + h * DK;

    int tid = threadIdx.x, lane = tid & 31, warp = tid >> 5;
    int wm = warp >> 1, wn = warp & 1;
    int g = lane >> 2, tg = lane & 3;
    int m_l = tid & 127, part = tid >> 7;

    {
        const uint4* qp = (const uint4*)(Qb + (size_t)(bq + m_l) * DM + part * 32);
        const uint4* kp = (const uint4*)(Kb + (size_t)(bk + m_l) * DM + part * 32);
        uint4* qd = (uint4*)(su.qk.Qs + m_l * SPITCH + part * 32);
        uint4* kd = (uint4*)(su.qk.Ks + m_l * SPITCH + part * 32);
#pragma unroll
        for (int j = 0; j < 4; j++) { qd[j] = qp[j]; kd[j] = kp[j]; }
    }
    __syncthreads();

    float acc[2][8][4];
#pragma unroll
    for (int mt = 0; mt < 2; mt++)
#pragma unroll
        for (int nt = 0; nt < 8; nt++)
#pragma unroll
            for (int q = 0; q < 4; q++) acc[mt][nt][q] = 0.f;

#pragma unroll
    for (int ks16 = 0; ks16 < 64; ks16 += 16) {
        uint32_t a[2][4];
#pragma unroll
        for (int mt = 0; mt < 2; mt++) {
            int r = wm * 32 + mt * 16 + g;
            a[mt][0] = *(const uint32_t*)(su.qk.Qs + r*SPITCH + ks16 + tg*2);
            a[mt][1] = *(const uint32_t*)(su.qk.Qs + (r+8)*SPITCH + ks16 + tg*2);
            a[mt][2] = *(const uint32_t*)(su.qk.Qs + r*SPITCH + ks16 + 8 + tg*2);
            a[mt][3] = *(const uint32_t*)(su.qk.Qs + (r+8)*SPITCH + ks16 + 8 + tg*2);
        }
#pragma unroll
        for (int nt = 0; nt < 8; nt++) {
            int cn = wn * 64 + nt * 8 + g;
            uint32_t bfr[2];
            bfr[0] = *(const uint32_t*)(su.qk.Ks + cn*SPITCH + ks16 + tg*2);
            bfr[1] = *(const uint32_t*)(su.qk.Ks + cn*SPITCH + ks16 + 8 + tg*2);
#pragma unroll
            for (int mt = 0; mt < 2; mt++) mma16816(acc[mt][nt], a[mt], bfr);
        }
    }

    const unsigned char* mrow = mask + (size_t)b * SEQ * SEQ;
    float* Pb = P + (size_t)bh * SEQ * SEQ;

    // two rounds: stage 64 rows in smem, then coalesced masked writes
    int lr_o = tid & 63, cs = (tid >> 6) * 32;
#pragma unroll
    for (int round = 0; round < 2; round++) {
        __syncthreads();
        if ((wm >> 1) == round) {
#pragma unroll
            for (int mt = 0; mt < 2; mt++)
#pragma unroll
                for (int nt = 0; nt < 8; nt++)
#pragma unroll
                    for (int hh = 0; hh < 2; hh++) {
                        int lr = (wm & 1) * 32 + mt * 16 + g + hh * 8;
                        int c = wn * 64 + nt * 8 + tg * 2;
                        *(float2*)(su.stage + lr * STPITCH + c) =
                            make_float2(acc[mt][nt][hh*2], acc[mt][nt][hh*2+1]);
                    }
        }
        __syncthreads();
        {
            int q = bq + round * 64 + lr_o;
            const unsigned char* mp = mrow + (size_t)q * SEQ + bk + cs;
            uint4 mw0 = *(const uint4*)mp;
            uint4 mw1 = *(const uint4*)(mp + 16);
            uint32_t mws[8] = {mw0.x, mw0.y, mw0.z, mw0.w, mw1.x, mw1.y, mw1.z, mw1.w};
            float* op = Pb + (size_t)q * SEQ + bk + cs;
            const float* sp = su.stage + lr_o * STPITCH + cs;
#pragma unroll
            for (int j4 = 0; j4 < 8; j4++) {
                float4 v = *(const float4*)(sp + j4 * 4);
                uint32_t mb = mws[j4 >> 1] >> ((j4 & 1) * 16);
                v.x *= 0.125f; v.y *= 0.125f; v.z *= 0.125f; v.w *= 0.125f;
                if (mb & 0x000000FFu) v.x = -1e9f;
                if (mb & 0x0000FF00u) v.y = -1e9f;
                // next two bytes are in bits 16-31 of the shifted word only when j4 even;
                // recompute cleanly:
                uint32_t mbw = mws[j4 >> 1];
                int sh = (j4 & 1) * 16;
                if ((mbw >> (sh + 0)) & 0xFF) v.x = -1e9f;
                if ((mbw >> (sh + 8)) & 0xFF) v.y = -1e9f;
                // z,w bytes: they live in the next half-word
                uint32_t mbw2 = mws[j4 >> 1];
                if (((j4 & 1) ? (mws[(j4 >> 1)] >> 24) : (mbw2 >> 16)) & 0xFF) {}
                *(float4*)(op + j4 * 4) = v;
            }
            // The masking above is convoluted; redo simply and correctly:
#pragma unroll
            for (int j4 = 0; j4 < 8; j4++) {
                float4 v = *(const float4*)(op + j4 * 4);
                const unsigned char* mb = mp + j4 * 4;
                uint32_t w = mws[(j4 * 4) >> 2];
                if ((w >>  0) & 0xFF) v.x = -1e9f;
                if ((w >>  8) & 0xFF) v.y = -1e9f;
                if ((w >> 16) & 0xFF) v.z = -1e9f;
                if ((w >> 24) & 0xFF) v.w = -1e9f;
                (void)mb;
                *(float4*)(op + j4 * 4) = v;
            }
        }
    }
}

// ============================================================
// Row softmax over SEQ=2048, in place.
// ============================================================
__global__ __launch_bounds__(128) void softmax_kernel(float* __restrict__ P)
{
    size_t row = blockIdx.x;
    float* p = P + row * (size_t)SEQ;
    int tid = threadIdx.x;
    int lane = tid & 31, warp = tid >> 5;
    __shared__ float sred[4];

    float v[16];
    float m = -1e30f;
#pragma unroll
    for (int i = 0; i < 16; i++) {
        v[i] = p[tid + i * 128];
        m = fmaxf(m, v[i]);
    }
#pragma unroll
    for (int o = 16; o > 0; o >>= 1) m = fmaxf(m, __shfl_xor_sync(0xffffffffu, m, o));
    if (lane == 0) sred[warp] = m;
    __syncthreads();
    m = fmaxf(fmaxf(sred[0], sred[1]), fmaxf(sred[2], sred[3]));
    __syncthreads();

    float s = 0.f;
#pragma unroll
    for (int i = 0; i < 16; i++) {
        v[i] = __expf(v[i] - m);
        s += v[i];
    }
#pragma unroll
    for (int o = 16; o > 0; o >>= 1) s += __shfl_xor_sync(0xffffffffu, s, o);
    if (lane == 0) sred[warp] = s;
    __syncthreads();
    s = sred[0] + sred[1] + sred[2] + sred[3];
    float inv = 1.f / s;
#pragma unroll
    for (int i = 0; i < 16; i++) p[tid + i * 128] = v[i] * inv;
}

// ============================================================
// PV: ctx_h[b,s,h*64+d] = sum_k P * V. fp16 out.
// ============================================================
#define APITCH 40
#define VPITCH 68

__global__ __launch_bounds__(256) void pv_mma(
    const float* __restrict__ P, const __half* __restrict__ Vh,
    __half* __restrict__ ctxh)
{
    __shared__ __half Ps[2][128*APITCH];
    __shared__ uint32_t Vs[2][16*VPITCH];

    int bh = blockIdx.y, b = bh / NH, h = bh % NH;
    int bm = blockIdx.x * 128;
    const float* Pb = P + (size_t)bh * SEQ * SEQ;
    const __half* Vb = Vh + (size_t)(b * SEQ) * DM + h * DK;

    int tid = threadIdx.x, lane = tid & 31, warp = tid >> 5;
    int wm = warp >> 1, wn = warp & 1;
    int g = lane >> 2, tg = lane & 3;
    int m_l = tid & 127, ks = (tid >> 7) * 16;
    int d_l = tid & 63, k2b = (tid >> 6);

    float acc[2][4][4];
#pragma unroll
    for (int mt = 0; mt < 2; mt++)
#pragma unroll
        for (int nt = 0; nt < 4; nt++)
#pragma unroll
            for (int q = 0; q < 4; q++) acc[mt][nt][q] = 0.f;

    float pr[16];
    __half v0r[4], v1r[4];

#define GLPV(k0) { \
    const float* pp = Pb + (size_t)(bm + m_l) * SEQ + (k0) + ks; \
    _Pragma("unroll") \
    for (int q = 0; q < 4; q++) *(float4*)&pr[q*4] = *(const float4*)(pp + q*4); \
    _Pragma("unroll") \
    for (int j = 0; j < 4; j++) { \
        int k2 = k2b * 4 + j; \
        v0r[j] = Vb[(size_t)((k0) + 2*k2) * DM + d_l]; \
        v1r[j] = Vb[(size_t)((k0) + 2*k2 + 1) * DM + d_l]; } }

#define STPV(buf) { \
    uint32_t pk[8]; \
    _Pragma("unroll") \
    for (int q = 0; q < 8; q++) pk[q] = pack_h2(pr[2*q], pr[2*q+1]); \
    uint4* dst = (uint4*)(&Ps[buf][m_l*APITCH + ks]); \
    dst[0] = make_uint4(pk[0],pk[1],pk[2],pk[3]); \
    dst[1] = make_uint4(pk[4],pk[5],pk[6],pk[7]); \
    _Pragma("unroll") \
    for (int j = 0; j < 4; j++) { \
        int k2 = k2b * 4 + j; \
        __half2 hv; hv.x = v0r[j]; hv.y = v1r[j]; \
        Vs[buf][k2 * VPITCH + d_l] = *(uint32_t*)&hv; } }

    GLPV(0); STPV(0);
    __syncthreads();

    const int NC = SEQ / 32;
    for (int i = 0; i < NC; i++) {
        int buf = i & 1;
        if (i + 1 < NC) GLPV((i + 1) * 32);
#pragma unroll
        for (int ks16 = 0; ks16 < 32; ks16 += 16) {
            uint32_t a[2][4];
#pragma unroll
            for (int mt = 0; mt < 2; mt++) {
                int r = wm * 32 + mt * 16 + g;
                const __half* ab = &Ps[buf][0];
                a[mt][0] = *(const uint32_t*)(ab + r*APITCH + ks16 + tg*2);
                a[mt][1] = *(const uint32_t*)(ab + (r+8)*APITCH + ks16 + tg*2);
                a[mt][2] = *(const uint32_t*)(ab + r*APITCH + ks16 + 8 + tg*2);
                a[mt][3] = *(const uint32_t*)(ab + (r+8)*APITCH + ks16 + 8 + tg*2);
            }
#pragma unroll
            for (int nt = 0; nt < 4; nt++) {
                int dn = wn * 32 + nt * 8 + g;
                uint32_t bfr[2];
                bfr[0] = Vs[buf][((ks16>>1) + tg) * VPITCH + dn];
                bfr[1] = Vs[buf][((ks16>>1) + tg + 4) * VPITCH + dn];
#pragma unroll
                for (int mt = 0; mt < 2; mt++) mma16816(acc[mt][nt], a[mt], bfr);
            }
        }
        if (i + 1 < NC) STPV(1 - buf);
        __syncthreads();
    }
#undef GLPV
#undef STPV

#pragma unroll
    for (int mt = 0; mt < 2; mt++)
#pragma unroll
        for (int nt = 0; nt < 4; nt++) {
            int cn = wn * 32 + nt * 8 + tg * 2;
#pragma unroll
            for (int hh = 0; hh < 2; hh++) {
                int r = bm + wm * 32 + mt * 16 + g + hh * 8;
                *(__half2*)(ctxh + (size_t)(b * SEQ + r) * DM + h * DK + cn) =
                    __floats2half2_rn(acc[mt][nt][hh*2], acc[mt][nt][hh*2+1]);
            }
        }
}

// ============================================================
// LayerNorm over last dim (768); optional fp16 copy of output.
// ============================================================
template<int OUTH>
__global__ __launch_bounds__(256) void layernorm_kernel(
    const float* __restrict__ X, const float* __restrict__ gam,
    const float* __restrict__ bet, float* __restrict__ Y, __half* __restrict__ Yh)
{
    int row = blockIdx.x;
    const float* x = X + (size_t)row * DM;
    float* y = Y + (size_t)row * DM;
    int tid = threadIdx.x;
    int lane = tid & 31, warp = tid >> 5;
    __shared__ float sw[8];

    float v0 = x[tid], v1 = x[tid + 256], v2 = x[tid + 512];
    float s = v0 + v1 + v2;
#pragma unroll
    for (int o = 16; o > 0; o >>= 1) s += __shfl_xor_sync(0xffffffffu, s, o);
    if (lane == 0) sw[warp] = s;
    __syncthreads();
    s = 0.f;
#pragma unroll
    for (int w = 0; w < 8; w++) s += sw[w];
    float mean = s * (1.f / 768.f);
    __syncthreads();

    float d0 = v0 - mean, d1 = v1 - mean, d2 = v2 - mean;
    float sq = d0 * d0 + d1 * d1 + d2 * d2;
#pragma unroll
    for (int o = 16; o > 0; o >>= 1) sq += __shfl_xor_sync(0xffffffffu, sq, o);
    if (lane == 0) sw[warp] = sq;
    __syncthreads();
    sq = 0.f;
#pragma unroll
    for (int w = 0; w < 8; w++) sq += sw[w];
    float var = sq * (1.f / 768.f);
    float rstd = rsqrtf(var + 1e-5f);

    float o0 = d0 * rstd * gam[tid]       + bet[tid];
    float o1 = d1 * rstd * gam[tid + 256] + bet[tid + 256];
    float o2 = d2 * rstd * gam[tid + 512] + bet[tid + 512];
    y[tid] = o0; y[tid + 256] = o1; y[tid + 512] = o2;
    if (OUTH) {
        __half* yh = Yh + (size_t)row * DM;
        yh[tid] = __float2half(o0);
        yh[tid + 256] = __float2half(o1);
        yh[tid + 512] = __float2half(o2);
    }
}

// ============================================================
#define HG_SMEM 49152

extern "C" void kernel_launch(void* const* d_in, const int* in_sizes, int n_in,
                              void* d_out, int out_size)
{
    const float* x    = (const float*)d_in[0];
    const unsigned char* mask = (const unsigned char*)d_in[1];
    const float* Wq = (const float*)d_in[2];
    const float* bq = (const float*)d_in[3];
    const float* Wk = (const float*)d_in[4];
    const float* bk = (const float*)d_in[5];
    const float* Wv = (const float*)d_in[6];
    const float* bv = (const float*)d_in[7];
    const float* Wo = (const float*)d_in[8];
    const float* bo = (const float*)d_in[9];
    const float* ln1g = (const float*)d_in[10];
    const float* ln1b = (const float*)d_in[11];
    const float* W1 = (const float*)d_in[12];
    const float* b1 = (const float*)d_in[13];
    const float* W2 = (const float*)d_in[14];
    const float* b2 = (const float*)d_in[15];
    const float* ln2g = (const float*)d_in[16];
    const float* ln2b = (const float*)d_in[17];
    float* out = (float*)d_out;

    __half *xh, *Wqh, *Wkh, *Wvh, *Woh, *W1h, *W2h;
    __half *Qh, *Kh, *Vh, *ctxh, *aoh, *hh;
    float *Pd, *t0, *ao, *f;
    cudaGetSymbolAddress((void**)&xh,   g_xh);
    cudaGetSymbolAddress((void**)&Wqh,  g_Wqh);
    cudaGetSymbolAddress((void**)&Wkh,  g_Wkh);
    cudaGetSymbolAddress((void**)&Wvh,  g_Wvh);
    cudaGetSymbolAddress((void**)&Woh,  g_Woh);
    cudaGetSymbolAddress((void**)&W1h,  g_W1h);
    cudaGetSymbolAddress((void**)&W2h,  g_W2h);
    cudaGetSymbolAddress((void**)&Qh,   g_Qh);
    cudaGetSymbolAddress((void**)&Kh,   g_Kh);
    cudaGetSymbolAddress((void**)&Vh,   g_Vh);
    cudaGetSymbolAddress((void**)&ctxh, g_ctxh);
    cudaGetSymbolAddress((void**)&aoh,  g_aoh);
    cudaGetSymbolAddress((void**)&hh,   g_hh);
    cudaGetSymbolAddress((void**)&Pd,   g_P);
    cudaGetSymbolAddress((void**)&t0,   g_t0);
    cudaGetSymbolAddress((void**)&ao,   g_ao);
    cudaGetSymbolAddress((void**)&f,    g_f);

    cudaFuncSetAttribute(hgemm<0,0,1>, cudaFuncAttributeMaxDynamicSharedMemorySize, HG_SMEM);
    cudaFuncSetAttribute(hgemm<0,1,0>, cudaFuncAttributeMaxDynamicSharedMemorySize, HG_SMEM);
    cudaFuncSetAttribute(hgemm<1,0,1>, cudaFuncAttributeMaxDynamicSharedMemorySize, HG_SMEM);

    float* Pbuf = ((size_t)out_size >= (size_t)OUT_ELEMS + ATT_ELEMS)
                ? (out + OUT_ELEMS) : Pd;

    // fp16 pre-conversions
    f2h_kernel<<<(MROWS*DM)/1024, 256>>>(x,  xh);
    f2h_kernel<<<(DM*DM)/1024,  256>>>(Wq, Wqh);
    f2h_kernel<<<(DM*DM)/1024,  256>>>(Wk, Wkh);
    f2h_kernel<<<(DM*DM)/1024,  256>>>(Wv, Wvh);
    f2h_kernel<<<(DM*DM)/1024,  256>>>(Wo, Woh);
    f2h_kernel<<<(DM*DFF)/1024, 256>>>(W1, W1h);
    f2h_kernel<<<(DFF*DM)/1024, 256>>>(W2, W2h);

    dim3 g768(DM / 128, MROWS / 128);
    hgemm<0,0,1><<<g768, 256, HG_SMEM>>>(xh, Wqh, bq, nullptr, nullptr, Qh, MROWS, DM, DM);
    hgemm<0,0,1><<<g768, 256, HG_SMEM>>>(xh, Wkh, bk, nullptr, nullptr, Kh, MROWS, DM, DM);
    hgemm<0,0,1><<<g768, 256, HG_SMEM>>>(xh, Wvh, bv, nullptr, nullptr, Vh, MROWS, DM, DM);

    dim3 gs(SEQ / 128, SEQ / 128, BHN);
    scores_mma<<<gs, 256>>>(Qh, Kh, mask, Pbuf);
    softmax_kernel<<<BHN * SEQ, 128>>>(Pbuf);

    dim3 gpv(SEQ / 128, BHN);
    pv_mma<<<gpv, 256>>>(Pbuf, Vh, ctxh);

    hgemm<0,1,0><<<g768, 256, HG_SMEM>>>(ctxh, Woh, bo, x, t0, nullptr, MROWS, DM, DM);
    layernorm_kernel<1><<<MROWS, 256>>>(t0, ln1g, ln1b, ao, aoh);

    dim3 gff1(DFF / 128, MROWS / 128);
    hgemm<1,0,1><<<gff1, 256, HG_SMEM>>>(aoh, W1h, b1, nullptr, nullptr, hh, MROWS, DFF, DM);
    hgemm<0,1,0><<<g768, 256, HG_SMEM>>>(hh, W2h, b2, ao, f, nullptr, MROWS, DM, DFF);
    layernorm_kernel<0><<<MROWS, 256>>>(f, ln2g, ln2b, out, nullptr);
}